// round 11
// baseline (speedup 1.0000x reference)
#include <cuda_runtime.h>

#define BATCH 2048
#define TLEN  512
#define KLAB  24
#define FULLMASK 0xffffffffu

__device__ float g_scratch[BATCH];

typedef unsigned long long u64;

__device__ __forceinline__ u64 pack2(float lo, float hi) {
    u64 r;
    asm("mov.b64 %0, {%1, %2};" : "=l"(r) : "f"(lo), "f"(hi));
    return r;
}
__device__ __forceinline__ void unpack2(u64 v, float& lo, float& hi) {
    asm("mov.b64 {%0, %1}, %2;" : "=f"(lo), "=f"(hi) : "l"(v));
}
__device__ __forceinline__ void ffma2(u64& acc, u64 a, u64 b) {
    asm("fma.rn.f32x2 %0, %1, %2, %3;" : "=l"(acc) : "l"(a), "l"(b), "l"(acc));
}

// ---------------------------------------------------------------------------
// Forward kernel: 2 chains per warp, 12 active lanes per chain (of 16),
// 2 labels per lane. lane = 16*c + g; chain b = blockIdx.x*2 + c; lane owns
// labels 2g, 2g+1 (g < 12).
// Prob-domain recurrence with packed f32x2 FMAs:
//   acc2[j] += (M[j,2s],M[j,2s+1]) (x) (A[2s],A[2s+1])   for s = 0..11
//   A'[j]    = E[t,j] * (acc2[j].x + acc2[j].y)
// M = exp(trans); exact 2^k rescale every 4 steps; E pre-computed in the ring.
// ---------------------------------------------------------------------------
__global__ __launch_bounds__(32)
void crf_forward_kernel(const float* __restrict__ feats,
                        const float* __restrict__ trans,
                        const void* __restrict__ tags_any,
                        const int* __restrict__ start_ptr) {
    const int lane = threadIdx.x;
    const int g = lane & 15;       // position within chain group (0..11 active)
    const int c = lane >> 4;       // chain slot within warp (0,1)
    const int b = blockIdx.x * 2 + c;
    const int gsel = lane & 0x10;  // 16*c : base lane of my chain group
    const bool act = (g < 12);

    const int start = start_ptr ? *start_ptr : 22;

    // tags dtype probe (int64 LE, values 0..21 -> odd words all zero).
    const unsigned int* traw = (const unsigned int*)tags_any + (blockIdx.x & 31) * 64;
    const int tags64 = (__reduce_or_sync(FULLMASK, traw[2 * lane + 1]) == 0u) ? 1 : 0;

    // M rows for my 2 labels, packed along i in pairs:
    // Mp[r][s] = ( M[2g+r][2s], M[2g+r][2s+1] ),  M = exp(trans).
    // exp(-10000) underflows to exact 0 == the reference's masking.
    u64 Mp[2][12];
    #pragma unroll
    for (int r = 0; r < 2; r++) {
        const int row = act ? (2 * g + r) : 0;
        #pragma unroll
        for (int s = 0; s < 12; s++) {
            float lo = act ? __expf(trans[row * KLAB + 2 * s + 0]) : 0.0f;
            float hi = act ? __expf(trans[row * KLAB + 2 * s + 1]) : 0.0f;
            Mp[r][s] = pack2(lo, hi);
        }
    }

    const float* fbase = feats + (size_t)b * TLEN * KLAB;
    const float* fb    = fbase + 2 * g;   // my 2 labels (valid when act)

    // Analytic step 1: A[j] = exp(trans[j,start] + feat[1,j]).
    float A0 = 0.0f, A1 = 0.0f;
    if (act) {
        A0 = __expf(trans[(2 * g + 0) * KLAB + start] + fb[1 * KLAB + 0]);
        A1 = __expf(trans[(2 * g + 1) * KLAB + start] + fb[1 * KLAB + 1]);
    }

    int esum = 0;

    // Prefetch ring, distance 4, storing E = exp(feat) (MUFU off the chain).
    float ring[4][2];
    #pragma unroll
    for (int t = 2; t < 6; t++) {
        ring[t & 3][0] = act ? __expf(fb[(size_t)t * KLAB + 0]) : 0.0f;
        ring[t & 3][1] = act ? __expf(fb[(size_t)t * KLAB + 1]) : 0.0f;
    }

    #pragma unroll 4
    for (int t = 2; t < TLEN; t++) {
        const float E0 = ring[t & 3][0], E1 = ring[t & 3][1];
        if (t + 4 < TLEN) {
            ring[t & 3][0] = act ? __expf(fb[(size_t)(t + 4) * KLAB + 0]) : 0.0f;
            ring[t & 3][1] = act ? __expf(fb[(size_t)(t + 4) * KLAB + 1]) : 0.0f;
        }

        // Gather packed A pairs from the 12 source lanes of my chain group;
        // one shfl serves both chains (different src per lane).
        u64 acc0 = 0ull, acc1 = 0ull;   // (0.0, 0.0) packed
        #pragma unroll
        for (int s = 0; s < 12; s++) {
            const int src = gsel + s;
            const float alo = __shfl_sync(FULLMASK, A0, src);
            const float ahi = __shfl_sync(FULLMASK, A1, src);
            const u64 a2 = pack2(alo, ahi);
            ffma2(acc0, Mp[0][s], a2);
            ffma2(acc1, Mp[1][s], a2);
        }
        float x0, y0, x1, y1;
        unpack2(acc0, x0, y0);
        unpack2(acc1, x1, y1);
        A0 = E0 * (x0 + y0);
        A1 = E1 * (x1 + y1);

        // Exact 2^k rescale every 4 steps (max over the 16-lane group;
        // idle lanes hold 0, max stays > 0 via row 0 of M).
        if ((t & 3) == 0) {
            float mx = fmaxf(A0, A1);
            mx = fmaxf(mx, __shfl_xor_sync(FULLMASK, mx, 1));
            mx = fmaxf(mx, __shfl_xor_sync(FULLMASK, mx, 2));
            mx = fmaxf(mx, __shfl_xor_sync(FULLMASK, mx, 4));
            mx = fmaxf(mx, __shfl_xor_sync(FULLMASK, mx, 8));
            const int e = (int)((__float_as_uint(mx) >> 23) & 0xFF) - 127;
            const float scale = __uint_as_float((unsigned int)(127 - e) << 23); // 2^-e
            esum += e;
            A0 *= scale; A1 *= scale;
        }
    }

    // forward = log(sum_j A[j]) + esum*ln2 (sum over the 16-lane group).
    float s2 = A0 + A1;
    s2 += __shfl_xor_sync(FULLMASK, s2, 1);
    s2 += __shfl_xor_sync(FULLMASK, s2, 2);
    s2 += __shfl_xor_sync(FULLMASK, s2, 4);
    s2 += __shfl_xor_sync(FULLMASK, s2, 8);
    const float forward = __logf(s2) + (float)((double)esum * 0.6931471805599453);

    // gold score: all 16 lanes of the group, stride-16 over t.
    float gg = 0.0f;
    if (tags64) {
        const long long* tb = (const long long*)tags_any + (size_t)b * TLEN;
        for (int t = 1 + g; t < TLEN; t += 16) {
            const int tc = (int)tb[t];
            const int tp = (int)tb[t - 1];
            gg += trans[tc * KLAB + tp] + fbase[(size_t)t * KLAB + tc];
        }
    } else {
        const int* tb = (const int*)tags_any + (size_t)b * TLEN;
        for (int t = 1 + g; t < TLEN; t += 16) {
            const int tc = tb[t];
            const int tp = tb[t - 1];
            gg += trans[tc * KLAB + tp] + fbase[(size_t)t * KLAB + tc];
        }
    }
    gg += __shfl_xor_sync(FULLMASK, gg, 1);
    gg += __shfl_xor_sync(FULLMASK, gg, 2);
    gg += __shfl_xor_sync(FULLMASK, gg, 4);
    gg += __shfl_xor_sync(FULLMASK, gg, 8);

    if (g == 0) g_scratch[b] = forward - gg;
}

// ---------------------------------------------------------------------------
// Deterministic fixed-order mean reduction.
// ---------------------------------------------------------------------------
__global__ void reduce_kernel(float* __restrict__ out) {
    __shared__ float s[256];
    float v = 0.0f;
    for (int i = threadIdx.x; i < BATCH; i += 256) v += g_scratch[i];
    s[threadIdx.x] = v;
    __syncthreads();
    for (int o = 128; o > 0; o >>= 1) {
        if (threadIdx.x < o) s[threadIdx.x] += s[threadIdx.x + o];
        __syncthreads();
    }
    if (threadIdx.x == 0) out[0] = s[0] / (float)BATCH;
}

// ---------------------------------------------------------------------------
extern "C" void kernel_launch(void* const* d_in, const int* in_sizes, int n_in,
                              void* d_out, int out_size) {
    const float* feats = (const float*)d_in[0];
    const float* trans = (const float*)d_in[1];
    const void*  tags  = d_in[2];
    const int*   start = (n_in > 3) ? (const int*)d_in[3] : nullptr;
    float* out = (float*)d_out;

    crf_forward_kernel<<<BATCH / 2, 32>>>(feats, trans, tags, start);
    reduce_kernel<<<1, 256>>>(out);
}